// round 3
// baseline (speedup 1.0000x reference)
#include <cuda_runtime.h>
#include <math.h>

#define B 128
#define T 2048
#define D 64
#define H 128
#define O 32
#define TILE 16
#define NTHREADS 832   // 8+8+8+2 warps = 26 warps

// xp0 scratch (device global; zero-init .bss)
__device__ float g_s0[(size_t)B * T * H];

// ---------------------------------------------------------------------------
// packed f32x2 helpers + fast tanh
// ---------------------------------------------------------------------------
__device__ __forceinline__ unsigned long long ffma2(unsigned long long a,
                                                    unsigned long long b,
                                                    unsigned long long c) {
    unsigned long long d;
    asm("fma.rn.f32x2 %0, %1, %2, %3;" : "=l"(d) : "l"(a), "l"(b), "l"(c));
    return d;
}
__device__ __forceinline__ unsigned long long addf2(unsigned long long a,
                                                    unsigned long long b) {
    unsigned long long d;
    asm("add.rn.f32x2 %0, %1, %2;" : "=l"(d) : "l"(a), "l"(b));
    return d;
}
__device__ __forceinline__ float f2lo(unsigned long long v) {
    return __uint_as_float((unsigned)(v & 0xffffffffull));
}
__device__ __forceinline__ float f2hi(unsigned long long v) {
    return __uint_as_float((unsigned)(v >> 32));
}
__device__ __forceinline__ float tanh_fast(float x) {
    float y;
    asm("tanh.approx.f32 %0, %1;" : "=f"(y) : "f"(x));
    return y;
}

// ---------------------------------------------------------------------------
// Input projection (layer 0): xp0[b,t,j] = x[b,t,:]·W_ih0[j,:] + b_ih0 + b_hh0
// Only for t < lengths[b].
// ---------------------------------------------------------------------------
template <int K>
__global__ __launch_bounds__(128) void proj_kernel(
    const float* __restrict__ in,   // [B,T,K]
    float* __restrict__ out,        // [B,T,H]
    const float* __restrict__ W,    // [H,K]
    const float* __restrict__ b1,
    const float* __restrict__ b2,
    const int* __restrict__ lengths)
{
    constexpr int CT = 16;
    const int b  = blockIdx.y;
    const int t0 = blockIdx.x * CT;
    const int len = lengths[b];
    if (t0 >= len) return;

    const int j = threadIdx.x;
    __shared__ __align__(16) float xs[CT][K];

    unsigned long long wq[K / 2];
    {
        const ulonglong2* Wp = (const ulonglong2*)(W + (size_t)j * K);
#pragma unroll
        for (int i = 0; i < K / 4; ++i) {
            ulonglong2 v = Wp[i];
            wq[2 * i] = v.x; wq[2 * i + 1] = v.y;
        }
    }
    const float bias = b1[j] + b2[j];

    const int nt = min(CT, len - t0);
    const float* inp = in + ((size_t)b * T + t0) * K;
    for (int idx = j; idx < nt * K / 4; idx += 128)
        ((float4*)xs)[idx] = ((const float4*)inp)[idx];
    __syncthreads();

    for (int tt = 0; tt < nt; ++tt) {
        unsigned long long acc0 = 0ull, acc1 = 0ull;
        const ulonglong2* xr = (const ulonglong2*)&xs[tt][0];
#pragma unroll
        for (int i = 0; i < K / 4; ++i) {
            ulonglong2 hv = xr[i];
            acc0 = ffma2(wq[2 * i], hv.x, acc0);
            acc1 = ffma2(wq[2 * i + 1], hv.y, acc1);
        }
        float s = (f2lo(acc0) + f2hi(acc0)) + (f2lo(acc1) + f2hi(acc1));
        out[((size_t)b * T + t0 + tt) * H + j] = bias + s;
    }
}

// ---------------------------------------------------------------------------
// Fused pipelined scan: one CTA per batch row, 4 stage-groups in wavefront.
//   A (w 0-7):  h1[i]   = tanh(xp0[i] + Whh0·h1[i-1])
//   B (w 8-15): xp1[i-1] = Wih1·h1[i-1] + b_ih1 + b_hh1
//   C (w16-23): h2[i-2] = tanh(xp1[i-2] + Whh1·h2[i-3])
//   D (w24-25): out[i-3] = Wfc·h2[i-3] + b_fc
// One __syncthreads per iteration; depth-2 ring buffers in shared.
// Each output row is computed by a lane pair (2-way k-split, k = 4*half+8*i),
// reduced with one shfl.xor. Weights live in registers as f32x2 pairs.
// ---------------------------------------------------------------------------
__global__ __launch_bounds__(NTHREADS, 1) void fused_kernel(
    const float* __restrict__ xp0,   // [B,T,H]
    const float* __restrict__ Whh0,
    const float* __restrict__ Wih1,
    const float* __restrict__ Whh1,
    const float* __restrict__ b_ih1,
    const float* __restrict__ b_hh1,
    const float* __restrict__ Wfc,   // [O,H]
    const float* __restrict__ bfc,   // [O]
    const int* __restrict__ lengths,
    float* __restrict__ out)         // [B,T,O]
{
    const int b    = blockIdx.x;
    const int tid  = threadIdx.x;
    const int len  = lengths[b];
    const int w    = tid >> 5;

    __shared__ float h1r[2][H];
    __shared__ float xp1r[2][H];
    __shared__ float h2r[2][H];
    __shared__ __align__(16) float xs[2][TILE * H];
    __shared__ float4 shb[O / 4];

    // group: 0=A,1=B,2=C,3=D ; group index == pipeline delay
    const int group = (w < 8) ? 0 : (w < 16) ? 1 : (w < 24) ? 2 : 3;
    const int gtid  = tid - ((group == 0) ? 0 : (group == 1) ? 256 :
                             (group == 2) ? 512 : 768);
    const int jr    = gtid >> 1;       // output row (A/B/C: 0..127, D: 0..31)
    const int half  = gtid & 1;        // k-half

    const float* Wsel = (group == 0) ? Whh0 : (group == 1) ? Wih1 :
                        (group == 2) ? Whh1 : Wfc;

    // weights: 64 floats, k = 4*half + 8*i (+0..3), packed f32x2
    unsigned long long wq[32];
    {
        const float* wrow = Wsel + (size_t)jr * H + 4 * half;
#pragma unroll
        for (int i = 0; i < 16; ++i) {
            ulonglong2 v = *(const ulonglong2*)(wrow + 8 * i);
            wq[2 * i] = v.x; wq[2 * i + 1] = v.y;
        }
    }

    float bias = 0.0f;
    if (group == 1) bias = b_ih1[jr] + b_hh1[jr];
    if (group == 3) bias = bfc[jr];

    // ring init + bias staging
    if (tid < H) { h1r[1][tid] = 0.0f; h2r[1][tid] = 0.0f; }
    if (tid >= H && tid < H + O / 4) shb[tid - H] = ((const float4*)bfc)[tid - H];

    // ---- xp0 tile pipeline (group A only) ----
    const float* xbase = xp0 + (size_t)b * T * H;
    float4 ra, rb;
    int f0 = gtid, f1 = gtid + 256;          // float4 slots within a tile
    int s0o = (f0 >> 5) * H + (f0 & 31) * 4;
    int s1o = (f1 >> 5) * H + (f1 & 31) * 4;
    if (group == 0) {
        *(float4*)&xs[0][s0o] = *(const float4*)(xbase + s0o);        // tile 0
        *(float4*)&xs[0][s1o] = *(const float4*)(xbase + s1o);
        ra = *(const float4*)(xbase + TILE * H + s0o);                // tile 1
        rb = *(const float4*)(xbase + TILE * H + s1o);
    }
    __syncthreads();

    const int iters = len + 3;
    float* obase = out + (size_t)b * T * O;

    for (int i = 0; i < iters; ++i) {
        if ((unsigned)(i - group) < (unsigned)len) {
            const float* src = ((group < 2) ? h1r[(i + 1) & 1]
                                            : h2r[(i + 1) & 1]) + 4 * half;
            unsigned long long a0 = 0ull, a1 = 0ull, a2 = 0ull, a3 = 0ull;
#pragma unroll
            for (int k = 0; k < 16; k += 2) {
                ulonglong2 hv0 = *(const ulonglong2*)(src + 8 * k);
                ulonglong2 hv1 = *(const ulonglong2*)(src + 8 * k + 8);
                a0 = ffma2(wq[2 * k],     hv0.x, a0);
                a1 = ffma2(wq[2 * k + 1], hv0.y, a1);
                a2 = ffma2(wq[2 * k + 2], hv1.x, a2);
                a3 = ffma2(wq[2 * k + 3], hv1.y, a3);
            }
            a0 = addf2(a0, a2);
            a1 = addf2(a1, a3);
            float s = (f2lo(a0) + f2hi(a0)) + (f2lo(a1) + f2hi(a1));
            s += __shfl_xor_sync(0xffffffffu, s, 1);

            if (half == 0) {
                if (group == 0) {
                    float v = tanh_fast(s + xs[(i >> 4) & 1][(i & 15) * H + jr]);
                    h1r[i & 1][jr] = v;
                } else if (group == 1) {
                    xp1r[(i + 1) & 1][jr] = s + bias;
                } else if (group == 2) {
                    float v = tanh_fast(s + xp1r[i & 1][jr]);
                    h2r[i & 1][jr] = v;
                } else {
                    obase[(size_t)(i - 3) * O + jr] = s + bias;
                }
            }
        }

        // tile commit + prefetch (A group, every 16 iters)
        if (group == 0 && (i & 15) == 15) {
            int cb = ((i >> 4) + 1) & 1;
            *(float4*)&xs[cb][s0o] = ra;
            *(float4*)&xs[cb][s1o] = rb;
            int base = ((i >> 4) + 2) * TILE;
            if (base + (f0 >> 5) < T) ra = *(const float4*)(xbase + base * H + s0o);
            if (base + (f1 >> 5) < T) rb = *(const float4*)(xbase + base * H + s1o);
        }
        __syncthreads();
    }

    // padded rows: out[b, t>=len, :] = b_fc
    {
        float4* orow = (float4*)(obase + (size_t)len * O);
        const int n4 = (T - len) * (O / 4);
        for (int idx = tid; idx < n4; idx += NTHREADS)
            orow[idx] = shb[idx & 7];
    }
}

// ---------------------------------------------------------------------------
extern "C" void kernel_launch(void* const* d_in, const int* in_sizes, int n_in,
                              void* d_out, int out_size)
{
    const float* x      = (const float*)d_in[0];
    const int*   lens   = (const int*)  d_in[1];
    const float* W_ih0  = (const float*)d_in[2];
    const float* W_hh0  = (const float*)d_in[3];
    const float* b_ih0  = (const float*)d_in[4];
    const float* b_hh0  = (const float*)d_in[5];
    const float* W_ih1  = (const float*)d_in[6];
    const float* W_hh1  = (const float*)d_in[7];
    const float* b_ih1  = (const float*)d_in[8];
    const float* b_hh1  = (const float*)d_in[9];
    const float* W_fc   = (const float*)d_in[10];
    const float* b_fc   = (const float*)d_in[11];
    float* out = (float*)d_out;

    float* s0;
    cudaGetSymbolAddress((void**)&s0, g_s0);

    dim3 pgrid(T / 16, B);
    proj_kernel<D><<<pgrid, 128>>>(x, s0, W_ih0, b_ih0, b_hh0, lens);
    fused_kernel<<<B, NTHREADS>>>(s0, W_hh0, W_ih1, W_hh1,
                                  b_ih1, b_hh1, W_fc, b_fc, lens, out);
}